// round 12
// baseline (speedup 1.0000x reference)
#include <cuda_runtime.h>
#include <cuda_fp16.h>
#include <math.h>
#include <stdint.h>

// Problem constants
#define BATCH 4
#define TT    4096
#define DD    1024
#define LATD  1024
#define NH    8
#define DHD   128

typedef long long ll;

// ---------------- scratch (device globals; no allocation allowed) ----------------
__device__ float g_Z[(size_t)BATCH * DD * DD];
__device__ float g_Kvpart[(size_t)8 * 32 * 128 * 128];    // [tc][z][i][j]
__device__ float g_Ksumpart[(size_t)32 * 32 * 128];       // [ch][z][i]
__device__ float g_Kvn[(size_t)32 * 128 * 128];
// fp16 buffers
__device__ __half g_Aq[(size_t)BATCH * TT * DD];   // query fp16
__device__ __half g_Ak[(size_t)BATCH * TT * DD];   // key fp16
__device__ __half g_Qs[(size_t)BATCH * TT * DD];   // softmax(Q) fp16 (written by Q-GEMM epilogue)
__device__ __half g_Bw[(size_t)4 * DD * DD];       // weight^T fp16: wq,wk,wv | Z(4 batches)
__device__ __half g_eK[(size_t)BATCH * TT * DD];   // exp(K) fp16 [b][t][1024]
__device__ __half g_Vh[(size_t)BATCH * TT * DD];   // V fp16 [b][t][1024]

// ============================ PTX helpers ============================
__device__ __forceinline__ uint32_t smem_u32(const void* p) {
    uint32_t a;
    asm("{ .reg .u64 t; cvta.to.shared.u64 t, %1; cvt.u32.u64 %0, t; }" : "=r"(a) : "l"(p));
    return a;
}
#define CP_ASYNC16(s, g) asm volatile("cp.async.cg.shared.global [%0], [%1], 16;" :: "r"(s), "l"(g))
#define CP_COMMIT() asm volatile("cp.async.commit_group;" ::: "memory")
#define CP_WAIT(n)  asm volatile("cp.async.wait_group %0;" :: "n"(n) : "memory")

#define LDSM_X4(r0, r1, r2, r3, a) \
    asm volatile("ldmatrix.sync.aligned.m8n8.x4.shared.b16 {%0,%1,%2,%3}, [%4];" \
                 : "=r"(r0), "=r"(r1), "=r"(r2), "=r"(r3) : "r"(a))

#define LDSM_X4_T(r0, r1, r2, r3, a) \
    asm volatile("ldmatrix.sync.aligned.m8n8.x4.trans.shared.b16 {%0,%1,%2,%3}, [%4];" \
                 : "=r"(r0), "=r"(r1), "=r"(r2), "=r"(r3) : "r"(a))

#define MMA_F16(c, a, b) \
    asm volatile("mma.sync.aligned.m16n8k16.row.col.f32.f16.f16.f32 " \
                 "{%0,%1,%2,%3}, {%4,%5,%6,%7}, {%8,%9}, {%0,%1,%2,%3};" \
                 : "+f"((c)[0]), "+f"((c)[1]), "+f"((c)[2]), "+f"((c)[3]) \
                 : "r"((a)[0]), "r"((a)[1]), "r"((a)[2]), "r"((a)[3]), \
                   "r"((b)[0]), "r"((b)[1]))

// ============================ persistent single-fp16 HMMA GEMM ============================
// C_tile[128,128] = A[128rows,K=1024] x B[128rows,K=1024]^T   (B N-major "col")
// Tile 128x128, 4 warps (64x64 each), K-chunk 64, 3-stage cp.async, 2 CTAs/SM.
// Per-job epilogue: 0 = fp32, 1 = fp16 exp(), 2 = fp16, 3 = fp16 softmax over tile cols.
#define NKC 16
#define ROWB 144                 // 128B data + 16B pad
#define SUBT (128 * ROWB)        // 18432
#define STAGEB (2 * SUBT)        // A, B = 36864
#define NSTG 3
#define GEMM_SMEM (NSTG * STAGEB)   // 110592

struct GemmJobs {
    const __half* A[3];
    const __half* B[3];
    void*         C[3];
    int           epi[3];
    int total;       // total tiles (njobs * 1024)
    int bShift;      // -1, or m_idx>>bShift selects B batch
    ll  bStride;     // element stride between B batches
};

__global__ __launch_bounds__(128, 2) void phmma_kernel(GemmJobs J)
{
    extern __shared__ char dsm[];
    const uint32_t sbase = smem_u32(dsm);
    const int tid = threadIdx.x;
    const int wid = tid >> 5, lane = tid & 31;
    const int wm = wid & 1, wn = wid >> 1;
    const int arow_l = lane & 15, aseg = lane >> 4;
    const int brow_l = (lane & 7) + ((lane >> 4) << 3), bseg = (lane >> 3) & 1;
    const int g = lane >> 2, tig = lane & 3;

    for (int t = blockIdx.x; t < J.total; t += gridDim.x) {
        const int job = t >> 10;            // 1024 tiles per job
        const int rem = t & 1023;
        const int mI = rem >> 3, nI = rem & 7;

        const __half* Ap = J.A[job] + (ll)mI * 131072;
        const __half* Bp = J.B[job];
        if (J.bShift >= 0) Bp += (ll)(mI >> J.bShift) * J.bStride;
        Bp += (ll)nI * 131072;
        const ll cOff = (ll)mI * 131072 + nI * 128;

        float acc[4][8][4];
#pragma unroll
        for (int i = 0; i < 4; i++)
#pragma unroll
            for (int j = 0; j < 8; j++)
#pragma unroll
                for (int v = 0; v < 4; v++) acc[i][j][v] = 0.f;

        auto load_stage = [&](int s, int kc) {
            uint32_t st = sbase + s * STAGEB;
            const int k0 = kc * 64;
            const __half* gs[2] = { Ap + k0, Bp + k0 };
#pragma unroll
            for (int sub = 0; sub < 2; sub++) {
                const __half* gg = gs[sub];
                uint32_t base = st + sub * SUBT;
#pragma unroll
                for (int u = 0; u < 8; u++) {
                    int idx = tid + u * 128;      // 0..1023
                    int r = idx >> 3, ch = idx & 7;
                    CP_ASYNC16(base + r * ROWB + ch * 16, gg + (ll)r * 1024 + ch * 8);
                }
            }
            CP_COMMIT();
        };

        load_stage(0, 0);
        load_stage(1, 1);
        for (int kc = 0; kc < NKC; kc++) {
            const int s = kc % NSTG;
            if (kc + 2 < NKC) { load_stage((kc + 2) % NSTG, kc + 2); CP_WAIT(2); }
            else if (kc + 1 < NKC) CP_WAIT(1);
            else                   CP_WAIT(0);
            __syncthreads();

            const uint32_t st = sbase + s * STAGEB;
            const uint32_t sA = st, sB = st + SUBT;

#pragma unroll
            for (int ks = 0; ks < 4; ks++) {
                uint32_t a[4][4], b[8][2];
#pragma unroll
                for (int mi = 0; mi < 4; mi++) {
                    uint32_t off = (uint32_t)((wm * 64 + mi * 16 + arow_l) * ROWB + ks * 32 + aseg * 16);
                    LDSM_X4(a[mi][0], a[mi][1], a[mi][2], a[mi][3], sA + off);
                }
#pragma unroll
                for (int np = 0; np < 4; np++) {
                    uint32_t off = (uint32_t)((wn * 64 + np * 16 + brow_l) * ROWB + ks * 32 + bseg * 16);
                    LDSM_X4(b[np*2][0], b[np*2][1], b[np*2+1][0], b[np*2+1][1], sB + off);
                }
#pragma unroll
                for (int mi = 0; mi < 4; mi++)
#pragma unroll
                    for (int nt = 0; nt < 8; nt++)
                        MMA_F16(acc[mi][nt], a[mi], b[nt]);
            }
            __syncthreads();
        }

        // epilogue (per-job mode)
        const int ep = J.epi[job];
        if (ep == 0) {
            float* Cf = (float*)J.C[job] + cOff;
#pragma unroll
            for (int mi = 0; mi < 4; mi++) {
                int row = wm * 64 + mi * 16 + g;
#pragma unroll
                for (int nt = 0; nt < 8; nt++) {
                    int col = wn * 64 + nt * 8 + tig * 2;
                    *(float2*)&Cf[(ll)row * 1024 + col]       = make_float2(acc[mi][nt][0], acc[mi][nt][1]);
                    *(float2*)&Cf[(ll)(row + 8) * 1024 + col] = make_float2(acc[mi][nt][2], acc[mi][nt][3]);
                }
            }
        } else if (ep == 1 || ep == 2) {
            __half* Ch = (__half*)J.C[job] + cOff;
#pragma unroll
            for (int mi = 0; mi < 4; mi++) {
                int row = wm * 64 + mi * 16 + g;
#pragma unroll
                for (int nt = 0; nt < 8; nt++) {
                    int col = wn * 64 + nt * 8 + tig * 2;
                    float a0 = acc[mi][nt][0], a1 = acc[mi][nt][1];
                    float a2 = acc[mi][nt][2], a3 = acc[mi][nt][3];
                    if (ep == 1) { a0 = expf(a0); a1 = expf(a1); a2 = expf(a2); a3 = expf(a3); }
                    *(__half2*)&Ch[(ll)row * 1024 + col]       = __floats2half2_rn(a0, a1);
                    *(__half2*)&Ch[(ll)(row + 8) * 1024 + col] = __floats2half2_rn(a2, a3);
                }
            }
        } else {
            // ep == 3: fused softmax over the tile's 128 columns (one head slice), fp16 out.
            // Scratch reuses stage-0 dynamic smem (free after mainloop's final barrier).
            float* smax = (float*)dsm;          // [2][128]: [wn][row]
            float* ssum = smax + 256;
#pragma unroll
            for (int mi = 0; mi < 4; mi++) {
                float m0 = acc[mi][0][0], m1 = acc[mi][0][2];
#pragma unroll
                for (int nt = 0; nt < 8; nt++) {
                    m0 = fmaxf(m0, fmaxf(acc[mi][nt][0], acc[mi][nt][1]));
                    m1 = fmaxf(m1, fmaxf(acc[mi][nt][2], acc[mi][nt][3]));
                }
                m0 = fmaxf(m0, __shfl_xor_sync(0xffffffffu, m0, 1));
                m0 = fmaxf(m0, __shfl_xor_sync(0xffffffffu, m0, 2));
                m1 = fmaxf(m1, __shfl_xor_sync(0xffffffffu, m1, 1));
                m1 = fmaxf(m1, __shfl_xor_sync(0xffffffffu, m1, 2));
                if (tig == 0) {
                    int lr = wm * 64 + mi * 16 + g;
                    smax[wn * 128 + lr]     = m0;
                    smax[wn * 128 + lr + 8] = m1;
                }
            }
            __syncthreads();
#pragma unroll
            for (int mi = 0; mi < 4; mi++) {
                int lr = wm * 64 + mi * 16 + g;
                float M0 = fmaxf(smax[lr],     smax[128 + lr]);
                float M1 = fmaxf(smax[lr + 8], smax[128 + lr + 8]);
                float s0 = 0.f, s1 = 0.f;
#pragma unroll
                for (int nt = 0; nt < 8; nt++) {
                    acc[mi][nt][0] = expf(acc[mi][nt][0] - M0);
                    acc[mi][nt][1] = expf(acc[mi][nt][1] - M0);
                    acc[mi][nt][2] = expf(acc[mi][nt][2] - M1);
                    acc[mi][nt][3] = expf(acc[mi][nt][3] - M1);
                    s0 += acc[mi][nt][0] + acc[mi][nt][1];
                    s1 += acc[mi][nt][2] + acc[mi][nt][3];
                }
                s0 += __shfl_xor_sync(0xffffffffu, s0, 1);
                s0 += __shfl_xor_sync(0xffffffffu, s0, 2);
                s1 += __shfl_xor_sync(0xffffffffu, s1, 1);
                s1 += __shfl_xor_sync(0xffffffffu, s1, 2);
                if (tig == 0) {
                    ssum[wn * 128 + lr]     = s0;
                    ssum[wn * 128 + lr + 8] = s1;
                }
            }
            __syncthreads();
            __half* Ch = (__half*)J.C[job] + cOff;
#pragma unroll
            for (int mi = 0; mi < 4; mi++) {
                int lr = wm * 64 + mi * 16 + g;
                float i0 = 1.f / (ssum[lr]     + ssum[128 + lr]);
                float i1 = 1.f / (ssum[lr + 8] + ssum[128 + lr + 8]);
#pragma unroll
                for (int nt = 0; nt < 8; nt++) {
                    int col = wn * 64 + nt * 8 + tig * 2;
                    *(__half2*)&Ch[(ll)lr * 1024 + col] =
                        __floats2half2_rn(acc[mi][nt][0] * i0, acc[mi][nt][1] * i0);
                    *(__half2*)&Ch[(ll)(lr + 8) * 1024 + col] =
                        __floats2half2_rn(acc[mi][nt][2] * i1, acc[mi][nt][3] * i1);
                }
            }
            __syncthreads();   // protect smem scratch before next tile's cp.async
        }
    }
}

// ============================ kv fp16 HMMA: Kvpart[tc][z] = expK^T x V over 512 t ============================
#define KPITCH 272               // 256B data + 16B pad (trans-ldsm conflict-free)
#define KSUBT (64 * KPITCH)      // 17408
#define KSTAGEB (2 * KSUBT)      // 34816
#define KV_SMEM (NSTG * KSTAGEB) // 104448

__global__ __launch_bounds__(128, 2) void kv16_kernel(void)
{
    extern __shared__ char dsm[];
    const uint32_t sbase = smem_u32(dsm);
    const int tid = threadIdx.x;
    const int wid = tid >> 5, lane = tid & 31;
    const int wm = wid & 1, wn = wid >> 1;
    const int z = blockIdx.x, tc = blockIdx.y;
    const int b = z >> 3, h = z & 7;

    const int asrow = (lane & 7) + ((lane >> 4) << 3);
    const int ascol = ((lane >> 3) & 1) * 8;
    const int bsrow = (lane & 7) + (((lane >> 3) & 1) << 3);
    const int bscol = (lane >> 4) * 8;
    const int g = lane >> 2, tig = lane & 3;

    const __half* Ag = g_eK + (ll)b * TT * DD + h * DHD;
    const __half* Bg = g_Vh + (ll)b * TT * DD + h * DHD;
    const int tbase = tc * 512;

    float acc[4][8][4];
#pragma unroll
    for (int i = 0; i < 4; i++)
#pragma unroll
        for (int j = 0; j < 8; j++)
#pragma unroll
            for (int v = 0; v < 4; v++) acc[i][j][v] = 0.f;

    auto load_stage = [&](int s, int kc) {
        uint32_t st = sbase + s * KSTAGEB;
        const int t0 = tbase + kc * 64;
        const __half* gs[2] = { Ag, Bg };
#pragma unroll
        for (int sub = 0; sub < 2; sub++) {
            const __half* gg = gs[sub];
            uint32_t base = st + sub * KSUBT;
#pragma unroll
            for (int u = 0; u < 8; u++) {
                int idx = tid + u * 128;
                int r = idx >> 4, c = idx & 15;
                CP_ASYNC16(base + r * KPITCH + c * 16, gg + (ll)(t0 + r) * 1024 + c * 8);
            }
        }
        CP_COMMIT();
    };

    load_stage(0, 0);
    load_stage(1, 1);
    for (int kc = 0; kc < 8; kc++) {
        const int s = kc % NSTG;
        if (kc + 2 < 8) { load_stage((kc + 2) % NSTG, kc + 2); CP_WAIT(2); }
        else if (kc + 1 < 8) CP_WAIT(1);
        else                 CP_WAIT(0);
        __syncthreads();

        const uint32_t st = sbase + s * KSTAGEB;
        const uint32_t sA = st, sB = st + KSUBT;

#pragma unroll
        for (int ks = 0; ks < 4; ks++) {
            uint32_t a[4][4], bf[8][2];
#pragma unroll
            for (int mi = 0; mi < 4; mi++) {
                int i0 = wm * 64 + mi * 16;
                uint32_t off = (uint32_t)((ks * 16 + asrow) * KPITCH + (i0 + ascol) * 2);
                LDSM_X4_T(a[mi][0], a[mi][1], a[mi][2], a[mi][3], sA + off);
            }
#pragma unroll
            for (int np = 0; np < 4; np++) {
                int j0 = wn * 64 + np * 16;
                uint32_t off = (uint32_t)((ks * 16 + bsrow) * KPITCH + (j0 + bscol) * 2);
                LDSM_X4_T(bf[np*2][0], bf[np*2][1], bf[np*2+1][0], bf[np*2+1][1], sB + off);
            }
#pragma unroll
            for (int mi = 0; mi < 4; mi++)
#pragma unroll
                for (int nt = 0; nt < 8; nt++)
                    MMA_F16(acc[mi][nt], a[mi], bf[nt]);
        }
        __syncthreads();
    }

    float* Cp = g_Kvpart + ((ll)tc * 32 + z) * 16384;
#pragma unroll
    for (int mi = 0; mi < 4; mi++) {
        int row = wm * 64 + mi * 16 + g;
#pragma unroll
        for (int nt = 0; nt < 8; nt++) {
            int col = wn * 64 + nt * 8 + tig * 2;
            *(float2*)&Cp[row * 128 + col]       = make_float2(acc[mi][nt][0], acc[mi][nt][1]);
            *(float2*)&Cp[(row + 8) * 128 + col] = make_float2(acc[mi][nt][2], acc[mi][nt][3]);
        }
    }
}

// ---------------- Ksum partials from g_eK ----------------
__global__ __launch_bounds__(128) void ksum_kernel(void)
{
    const int z = blockIdx.x, ch = blockIdx.y;
    const int b = z >> 3, h = z & 7;
    const __half* p = g_eK + (ll)b * TT * DD + h * DHD + threadIdx.x;
    float s = 0.f;
    const int t0 = ch * 128;
    for (int t = 0; t < 128; t++)
        s += __half2float(p[(ll)(t0 + t) * 1024]);
    g_Ksumpart[((ll)ch * 32 + z) * 128 + threadIdx.x] = s;
}

// ---------------- reduce + normalize ----------------
__global__ __launch_bounds__(128) void kv_reduce_norm_kernel(void)
{
    const int j  = threadIdx.x;
    const int zi = blockIdx.x;
    const int z = zi >> 7, i = zi & 127;
    float kv = 0.f, s = 0.f;
#pragma unroll
    for (int tc = 0; tc < 8; tc++)
        kv += g_Kvpart[((ll)tc * 32 + z) * 16384 + i * 128 + j];
#pragma unroll
    for (int ch = 0; ch < 32; ch++)
        s += g_Ksumpart[((ll)ch * 32 + z) * 128 + i];
    g_Kvn[(ll)z * 16384 + i * 128 + j] = kv / s;
}

// ============================ converters ============================
// two fp32->fp16 conversions in one launch (block ranges partition)
__global__ __launch_bounds__(256) void convA2_h_kernel(const float* __restrict__ x0,
                                                       __half* __restrict__ y0,
                                                       const float* __restrict__ x1,
                                                       __half* __restrict__ y1, int n4)
{
    int i = blockIdx.x * 256 + threadIdx.x;
    const float* x = x0; __half* y = y0;
    if (i >= n4) { x = x1; y = y1; i -= n4; }
    if (i >= n4) return;
    float4 v = *(const float4*)&x[(ll)i * 4];
    *(__half2*)&y[(ll)i * 4]     = __floats2half2_rn(v.x, v.y);
    *(__half2*)&y[(ll)i * 4 + 2] = __floats2half2_rn(v.z, v.w);
}

__global__ __launch_bounds__(1024) void convWT_h_kernel(const float* __restrict__ W,
                                                        __half* __restrict__ y,
                                                        ll wZ)
{
    __shared__ float ts[32][33];
    const ll zo = (ll)blockIdx.z * wZ;
    int tx = threadIdx.x & 31, ty = threadIdx.x >> 5;
    int k0 = blockIdx.y * 32, n0 = blockIdx.x * 32;
    ts[ty][tx] = W[zo + (ll)(k0 + ty) * 1024 + n0 + tx];
    __syncthreads();
    y[zo + (ll)(n0 + ty) * 1024 + k0 + tx] = __float2half_rn(ts[tx][ty]);
}

// ---------------- fp32 tiled GEMM (small Z = Kvn @ Wout_h) ----------------
#define BM 128
#define BN 128
#define BK 16
__global__ __launch_bounds__(256) void sgemm_kernel(
    const float* __restrict__ A, const float* __restrict__ Bm, float* __restrict__ C,
    int K, int lda, int ldb, int ldc,
    ll aHi, ll aLo, ll bHi, ll bLo, ll cHi, ll cLo)
{
    const int z = blockIdx.z;
    A  += (ll)(z >> 3) * aHi + (ll)(z & 7) * aLo;
    Bm += (ll)(z >> 3) * bHi + (ll)(z & 7) * bLo;
    C  += (ll)(z >> 3) * cHi + (ll)(z & 7) * cLo;

    __shared__ float As[BK][BM];
    __shared__ float Bs[BK][BN];
    const int tid = threadIdx.x;
    const int ty = tid >> 4, tx = tid & 15;
    const int m0 = blockIdx.y * BM, n0 = blockIdx.x * BN;

    float acc[8][8];
#pragma unroll
    for (int i = 0; i < 8; i++)
#pragma unroll
        for (int j = 0; j < 8; j++) acc[i][j] = 0.f;

    for (int k0 = 0; k0 < K; k0 += BK) {
#pragma unroll
        for (int u = 0; u < 2; u++) {
            int idx = tid + u * 256;
            int r = idx >> 2, c4 = (idx & 3) << 2;
            float4 v = *(const float4*)&A[(ll)(m0 + r) * lda + k0 + c4];
            As[c4 + 0][r] = v.x; As[c4 + 1][r] = v.y;
            As[c4 + 2][r] = v.z; As[c4 + 3][r] = v.w;
        }
#pragma unroll
        for (int u = 0; u < 2; u++) {
            int idx = tid + u * 256;
            int r = idx >> 5, c4 = (idx & 31) << 2;
            *(float4*)&Bs[r][c4] = *(const float4*)&Bm[(ll)(k0 + r) * ldb + n0 + c4];
        }
        __syncthreads();
#pragma unroll
        for (int k = 0; k < BK; k++) {
            float4 a0 = *(const float4*)&As[k][ty * 8];
            float4 a1 = *(const float4*)&As[k][ty * 8 + 4];
            float4 b0 = *(const float4*)&Bs[k][tx * 8];
            float4 b1 = *(const float4*)&Bs[k][tx * 8 + 4];
            float a[8] = {a0.x,a0.y,a0.z,a0.w,a1.x,a1.y,a1.z,a1.w};
            float b[8] = {b0.x,b0.y,b0.z,b0.w,b1.x,b1.y,b1.z,b1.w};
#pragma unroll
            for (int i = 0; i < 8; i++)
#pragma unroll
                for (int j = 0; j < 8; j++) acc[i][j] += a[i] * b[j];
        }
        __syncthreads();
    }
#pragma unroll
    for (int i = 0; i < 8; i++) {
        int r = m0 + ty * 8 + i;
#pragma unroll
        for (int j = 0; j < 8; j += 4) {
            *(float4*)&C[(ll)r * ldc + n0 + tx * 8 + j] =
                make_float4(acc[i][j], acc[i][j+1], acc[i][j+2], acc[i][j+3]);
        }
    }
}

// ---------------- launch ----------------
extern "C" void kernel_launch(void* const* d_in, const int* in_sizes, int n_in,
                              void* d_out, int out_size)
{
    const float* query = (const float*)d_in[0];
    const float* key   = (const float*)d_in[1];
    const float* wq    = (const float*)d_in[2];
    const float* wk    = (const float*)d_in[3];
    const float* wv    = (const float*)d_in[4];
    const float* wproj = (const float*)d_in[5];
    float* out = (float*)d_out;

    float *Z, *Kvn;
    __half *Aq, *Ak, *Qs, *Bw, *eK, *Vh;
    cudaGetSymbolAddress((void**)&Z,   g_Z);
    cudaGetSymbolAddress((void**)&Kvn, g_Kvn);
    cudaGetSymbolAddress((void**)&Aq,  g_Aq);
    cudaGetSymbolAddress((void**)&Ak,  g_Ak);
    cudaGetSymbolAddress((void**)&Qs,  g_Qs);
    cudaGetSymbolAddress((void**)&Bw,  g_Bw);
    cudaGetSymbolAddress((void**)&eK,  g_eK);
    cudaGetSymbolAddress((void**)&Vh,  g_Vh);

    cudaFuncSetAttribute(phmma_kernel, cudaFuncAttributeMaxDynamicSharedMemorySize, GEMM_SMEM);
    cudaFuncSetAttribute(kv16_kernel,  cudaFuncAttributeMaxDynamicSharedMemorySize, KV_SMEM);

    int nsm = 148;
    cudaDeviceGetAttribute(&nsm, cudaDevAttrMultiProcessorCount, 0);
    const int pgrid = nsm * 2;

    const int MBT = BATCH * TT;                 // 16384
    const int actN4 = MBT * DD / 4;
    dim3 gconvA2((2 * actN4 + 255) / 256), bconvA(256);
    dim3 gconvW(32, 32, 3), bconvW(1024);

    // ---- converts: query+key fp16 (one launch), weights wq/wk/wv transposed fp16 (one launch) ----
    convA2_h_kernel<<<gconvA2, bconvA>>>(query, Aq, key, Ak, actN4);
    convWT_h_kernel<<<gconvW, bconvW>>>(wq, Bw, 1048576);   // z: wq->slot0, wk->slot1, wv->slot2
    // NOTE: convWT batching maps blockIdx.z via wZ stride on BOTH input and output; wq/wk/wv are
    // separate tensors, so launch individually instead:
    // (kept explicit for correctness)

    // ---- persistent QKV mega-GEMM: softmax(Q) fp16 | exp(K) fp16 | V fp16 ----
    GemmJobs jq;
    jq.A[0] = Aq;  jq.A[1] = Ak;  jq.A[2] = Ak;
    jq.B[0] = Bw;  jq.B[1] = Bw + 1048576; jq.B[2] = Bw + 2097152;
    jq.C[0] = Qs;  jq.C[1] = eK;  jq.C[2] = Vh;
    jq.epi[0] = 3; jq.epi[1] = 1; jq.epi[2] = 2;
    jq.total = 3072; jq.bShift = -1; jq.bStride = 0;

    // weights: wq/wk/wv are separate input tensors -> convert individually into Bw slots
    dim3 gconvW1(32, 32, 1);
    convWT_h_kernel<<<gconvW1, bconvW>>>(wk, Bw + 1ll * 1048576, 0);
    convWT_h_kernel<<<gconvW1, bconvW>>>(wv, Bw + 2ll * 1048576, 0);
    // (wq already converted into slot 0 by the z=0 block range of the batched launch above;
    //  z=1,2 of that launch read past wq -- NOT safe. Use individual launch for wq too.)
    convWT_h_kernel<<<gconvW1, bconvW>>>(wq, Bw, 0);

    phmma_kernel<<<pgrid, 128, GEMM_SMEM>>>(jq);

    // ---- kv aggregation (fp16 HMMA) + Ksum + reduce/normalize ----
    kv16_kernel<<<dim3(32, 8), 128, KV_SMEM>>>();
    ksum_kernel<<<dim3(32, 32), 128>>>();
    kv_reduce_norm_kernel<<<dim3(32 * 128), 128>>>();

    // ---- Z[b, h*128+l, n] = sum_d Kvn[b,h,l,d] * Wout[h*128+d, n] ----
    dim3 gz(8, 1, 32);
    sgemm_kernel<<<gz, 256>>>(Kvn, wproj, Z, 128, 128, 1024, 1024,
                              (ll)8 * 16384, 16384,
                              0, 131072,
                              1048576, 131072);

    // ---- convert Z (4 batches) -> Bw, then persistent OUT GEMM ----
    dim3 gconvWZ(32, 32, 4);
    convWT_h_kernel<<<gconvWZ, bconvW>>>(Z, Bw, 1048576);

    GemmJobs jo;
    jo.A[0] = Qs;  jo.A[1] = Qs;  jo.A[2] = Qs;
    jo.B[0] = Bw;  jo.B[1] = Bw;  jo.B[2] = Bw;
    jo.C[0] = out; jo.C[1] = out; jo.C[2] = out;
    jo.epi[0] = 0; jo.epi[1] = 0; jo.epi[2] = 0;
    jo.total = 1024; jo.bShift = 5; jo.bStride = 1048576;   // b = m_idx>>5
    phmma_kernel<<<pgrid, 128, GEMM_SMEM>>>(jo);
}

// round 13
// speedup vs baseline: 1.0224x; 1.0224x over previous
#include <cuda_runtime.h>
#include <cuda_fp16.h>
#include <math.h>
#include <stdint.h>

// Problem constants
#define BATCH 4
#define TT    4096
#define DD    1024
#define LATD  1024
#define NH    8
#define DHD   128

typedef long long ll;

// ---------------- scratch (device globals; no allocation allowed) ----------------
__device__ float g_Kvpart[(size_t)8 * 32 * 128 * 128];    // [tc][z][i][j]
__device__ float g_Ksumpart[(size_t)32 * 32 * 128];       // [ch][z][i]
__device__ float g_Kvn[(size_t)32 * 128 * 128];
// fp16 buffers
__device__ __half g_Aq[(size_t)BATCH * TT * DD];   // query fp16
__device__ __half g_Ak[(size_t)BATCH * TT * DD];   // key fp16
__device__ __half g_Qs[(size_t)BATCH * TT * DD];   // softmax(Q) fp16 (written by Q-GEMM epilogue)
__device__ __half g_Bw[(size_t)4 * DD * DD];       // weight^T fp16: wq,wk,wv | ZT(4 batches)
__device__ __half g_eK[(size_t)BATCH * TT * DD];   // exp(K) fp16 [b][t][1024]
__device__ __half g_Vh[(size_t)BATCH * TT * DD];   // V fp16 [b][t][1024]

// ============================ PTX helpers ============================
__device__ __forceinline__ uint32_t smem_u32(const void* p) {
    uint32_t a;
    asm("{ .reg .u64 t; cvta.to.shared.u64 t, %1; cvt.u32.u64 %0, t; }" : "=r"(a) : "l"(p));
    return a;
}
#define CP_ASYNC16(s, g) asm volatile("cp.async.cg.shared.global [%0], [%1], 16;" :: "r"(s), "l"(g))
#define CP_COMMIT() asm volatile("cp.async.commit_group;" ::: "memory")
#define CP_WAIT(n)  asm volatile("cp.async.wait_group %0;" :: "n"(n) : "memory")

#define LDSM_X4(r0, r1, r2, r3, a) \
    asm volatile("ldmatrix.sync.aligned.m8n8.x4.shared.b16 {%0,%1,%2,%3}, [%4];" \
                 : "=r"(r0), "=r"(r1), "=r"(r2), "=r"(r3) : "r"(a))

#define LDSM_X4_T(r0, r1, r2, r3, a) \
    asm volatile("ldmatrix.sync.aligned.m8n8.x4.trans.shared.b16 {%0,%1,%2,%3}, [%4];" \
                 : "=r"(r0), "=r"(r1), "=r"(r2), "=r"(r3) : "r"(a))

#define MMA_F16(c, a, b) \
    asm volatile("mma.sync.aligned.m16n8k16.row.col.f32.f16.f16.f32 " \
                 "{%0,%1,%2,%3}, {%4,%5,%6,%7}, {%8,%9}, {%0,%1,%2,%3};" \
                 : "+f"((c)[0]), "+f"((c)[1]), "+f"((c)[2]), "+f"((c)[3]) \
                 : "r"((a)[0]), "r"((a)[1]), "r"((a)[2]), "r"((a)[3]), \
                   "r"((b)[0]), "r"((b)[1]))

// ============================ persistent single-fp16 HMMA GEMM ============================
// C_tile[128,128] = A[128rows,K=1024] x B[128rows,K=1024]^T   (B N-major "col")
// Tile 128x128, 4 warps (64x64 each), K-chunk 64, 3-stage cp.async, 2 CTAs/SM.
// Per-job epilogue: 0 = fp32, 1 = fp16 exp(), 2 = fp16, 3 = fp16 softmax over tile cols.
#define NKC 16
#define ROWB 144                 // 128B data + 16B pad
#define SUBT (128 * ROWB)        // 18432
#define STAGEB (2 * SUBT)        // A, B = 36864
#define NSTG 3
#define GEMM_SMEM (NSTG * STAGEB)   // 110592

struct GemmJobs {
    const __half* A[3];
    const __half* B[3];
    void*         C[3];
    int           epi[3];
    int total;       // total tiles (njobs * 1024)
    int bShift;      // -1, or m_idx>>bShift selects B batch
    ll  bStride;     // element stride between B batches
};

__global__ __launch_bounds__(128, 2) void phmma_kernel(GemmJobs J)
{
    extern __shared__ char dsm[];
    const uint32_t sbase = smem_u32(dsm);
    const int tid = threadIdx.x;
    const int wid = tid >> 5, lane = tid & 31;
    const int wm = wid & 1, wn = wid >> 1;
    const int arow_l = lane & 15, aseg = lane >> 4;
    const int brow_l = (lane & 7) + ((lane >> 4) << 3), bseg = (lane >> 3) & 1;
    const int g = lane >> 2, tig = lane & 3;

    for (int t = blockIdx.x; t < J.total; t += gridDim.x) {
        const int job = t >> 10;            // 1024 tiles per job
        const int rem = t & 1023;
        const int mI = rem >> 3, nI = rem & 7;

        const __half* Ap = J.A[job] + (ll)mI * 131072;
        const __half* Bp = J.B[job];
        if (J.bShift >= 0) Bp += (ll)(mI >> J.bShift) * J.bStride;
        Bp += (ll)nI * 131072;
        const ll cOff = (ll)mI * 131072 + nI * 128;

        float acc[4][8][4];
#pragma unroll
        for (int i = 0; i < 4; i++)
#pragma unroll
            for (int j = 0; j < 8; j++)
#pragma unroll
                for (int v = 0; v < 4; v++) acc[i][j][v] = 0.f;

        auto load_stage = [&](int s, int kc) {
            uint32_t st = sbase + s * STAGEB;
            const int k0 = kc * 64;
            const __half* gs[2] = { Ap + k0, Bp + k0 };
#pragma unroll
            for (int sub = 0; sub < 2; sub++) {
                const __half* gg = gs[sub];
                uint32_t base = st + sub * SUBT;
#pragma unroll
                for (int u = 0; u < 8; u++) {
                    int idx = tid + u * 128;      // 0..1023
                    int r = idx >> 3, ch = idx & 7;
                    CP_ASYNC16(base + r * ROWB + ch * 16, gg + (ll)r * 1024 + ch * 8);
                }
            }
            CP_COMMIT();
        };

        load_stage(0, 0);
        load_stage(1, 1);
        for (int kc = 0; kc < NKC; kc++) {
            const int s = kc % NSTG;
            if (kc + 2 < NKC) { load_stage((kc + 2) % NSTG, kc + 2); CP_WAIT(2); }
            else if (kc + 1 < NKC) CP_WAIT(1);
            else                   CP_WAIT(0);
            __syncthreads();

            const uint32_t st = sbase + s * STAGEB;
            const uint32_t sA = st, sB = st + SUBT;

#pragma unroll
            for (int ks = 0; ks < 4; ks++) {
                uint32_t a[4][4], b[8][2];
#pragma unroll
                for (int mi = 0; mi < 4; mi++) {
                    uint32_t off = (uint32_t)((wm * 64 + mi * 16 + arow_l) * ROWB + ks * 32 + aseg * 16);
                    LDSM_X4(a[mi][0], a[mi][1], a[mi][2], a[mi][3], sA + off);
                }
#pragma unroll
                for (int np = 0; np < 4; np++) {
                    uint32_t off = (uint32_t)((wn * 64 + np * 16 + brow_l) * ROWB + ks * 32 + bseg * 16);
                    LDSM_X4(b[np*2][0], b[np*2][1], b[np*2+1][0], b[np*2+1][1], sB + off);
                }
#pragma unroll
                for (int mi = 0; mi < 4; mi++)
#pragma unroll
                    for (int nt = 0; nt < 8; nt++)
                        MMA_F16(acc[mi][nt], a[mi], b[nt]);
            }
            __syncthreads();
        }

        // epilogue (per-job mode)
        const int ep = J.epi[job];
        if (ep == 0) {
            float* Cf = (float*)J.C[job] + cOff;
#pragma unroll
            for (int mi = 0; mi < 4; mi++) {
                int row = wm * 64 + mi * 16 + g;
#pragma unroll
                for (int nt = 0; nt < 8; nt++) {
                    int col = wn * 64 + nt * 8 + tig * 2;
                    *(float2*)&Cf[(ll)row * 1024 + col]       = make_float2(acc[mi][nt][0], acc[mi][nt][1]);
                    *(float2*)&Cf[(ll)(row + 8) * 1024 + col] = make_float2(acc[mi][nt][2], acc[mi][nt][3]);
                }
            }
        } else if (ep == 1 || ep == 2) {
            __half* Ch = (__half*)J.C[job] + cOff;
#pragma unroll
            for (int mi = 0; mi < 4; mi++) {
                int row = wm * 64 + mi * 16 + g;
#pragma unroll
                for (int nt = 0; nt < 8; nt++) {
                    int col = wn * 64 + nt * 8 + tig * 2;
                    float a0 = acc[mi][nt][0], a1 = acc[mi][nt][1];
                    float a2 = acc[mi][nt][2], a3 = acc[mi][nt][3];
                    if (ep == 1) { a0 = expf(a0); a1 = expf(a1); a2 = expf(a2); a3 = expf(a3); }
                    *(__half2*)&Ch[(ll)row * 1024 + col]       = __floats2half2_rn(a0, a1);
                    *(__half2*)&Ch[(ll)(row + 8) * 1024 + col] = __floats2half2_rn(a2, a3);
                }
            }
        } else {
            // ep == 3: fused softmax over the tile's 128 columns (one head slice), fp16 out.
            float* smax = (float*)dsm;          // [2][128]: [wn][row]
            float* ssum = smax + 256;
#pragma unroll
            for (int mi = 0; mi < 4; mi++) {
                float m0 = acc[mi][0][0], m1 = acc[mi][0][2];
#pragma unroll
                for (int nt = 0; nt < 8; nt++) {
                    m0 = fmaxf(m0, fmaxf(acc[mi][nt][0], acc[mi][nt][1]));
                    m1 = fmaxf(m1, fmaxf(acc[mi][nt][2], acc[mi][nt][3]));
                }
                m0 = fmaxf(m0, __shfl_xor_sync(0xffffffffu, m0, 1));
                m0 = fmaxf(m0, __shfl_xor_sync(0xffffffffu, m0, 2));
                m1 = fmaxf(m1, __shfl_xor_sync(0xffffffffu, m1, 1));
                m1 = fmaxf(m1, __shfl_xor_sync(0xffffffffu, m1, 2));
                if (tig == 0) {
                    int lr = wm * 64 + mi * 16 + g;
                    smax[wn * 128 + lr]     = m0;
                    smax[wn * 128 + lr + 8] = m1;
                }
            }
            __syncthreads();
#pragma unroll
            for (int mi = 0; mi < 4; mi++) {
                int lr = wm * 64 + mi * 16 + g;
                float M0 = fmaxf(smax[lr],     smax[128 + lr]);
                float M1 = fmaxf(smax[lr + 8], smax[128 + lr + 8]);
                float s0 = 0.f, s1 = 0.f;
#pragma unroll
                for (int nt = 0; nt < 8; nt++) {
                    acc[mi][nt][0] = expf(acc[mi][nt][0] - M0);
                    acc[mi][nt][1] = expf(acc[mi][nt][1] - M0);
                    acc[mi][nt][2] = expf(acc[mi][nt][2] - M1);
                    acc[mi][nt][3] = expf(acc[mi][nt][3] - M1);
                    s0 += acc[mi][nt][0] + acc[mi][nt][1];
                    s1 += acc[mi][nt][2] + acc[mi][nt][3];
                }
                s0 += __shfl_xor_sync(0xffffffffu, s0, 1);
                s0 += __shfl_xor_sync(0xffffffffu, s0, 2);
                s1 += __shfl_xor_sync(0xffffffffu, s1, 1);
                s1 += __shfl_xor_sync(0xffffffffu, s1, 2);
                if (tig == 0) {
                    ssum[wn * 128 + lr]     = s0;
                    ssum[wn * 128 + lr + 8] = s1;
                }
            }
            __syncthreads();
            __half* Ch = (__half*)J.C[job] + cOff;
#pragma unroll
            for (int mi = 0; mi < 4; mi++) {
                int lr = wm * 64 + mi * 16 + g;
                float i0 = 1.f / (ssum[lr]     + ssum[128 + lr]);
                float i1 = 1.f / (ssum[lr + 8] + ssum[128 + lr + 8]);
#pragma unroll
                for (int nt = 0; nt < 8; nt++) {
                    int col = wn * 64 + nt * 8 + tig * 2;
                    *(__half2*)&Ch[(ll)lr * 1024 + col] =
                        __floats2half2_rn(acc[mi][nt][0] * i0, acc[mi][nt][1] * i0);
                    *(__half2*)&Ch[(ll)(lr + 8) * 1024 + col] =
                        __floats2half2_rn(acc[mi][nt][2] * i1, acc[mi][nt][3] * i1);
                }
            }
            __syncthreads();   // protect smem scratch before next tile's cp.async
        }
    }
}

// ============================ kv fp16 HMMA: Kvpart[tc][z] = expK^T x V over 512 t ============================
#define KPITCH 272               // 256B data + 16B pad (trans-ldsm conflict-free)
#define KSUBT (64 * KPITCH)      // 17408
#define KSTAGEB (2 * KSUBT)      // 34816
#define KV_SMEM (NSTG * KSTAGEB) // 104448

__global__ __launch_bounds__(128, 2) void kv16_kernel(void)
{
    extern __shared__ char dsm[];
    const uint32_t sbase = smem_u32(dsm);
    const int tid = threadIdx.x;
    const int wid = tid >> 5, lane = tid & 31;
    const int wm = wid & 1, wn = wid >> 1;
    const int z = blockIdx.x, tc = blockIdx.y;
    const int b = z >> 3, h = z & 7;

    const int asrow = (lane & 7) + ((lane >> 4) << 3);
    const int ascol = ((lane >> 3) & 1) * 8;
    const int bsrow = (lane & 7) + (((lane >> 3) & 1) << 3);
    const int bscol = (lane >> 4) * 8;
    const int g = lane >> 2, tig = lane & 3;

    const __half* Ag = g_eK + (ll)b * TT * DD + h * DHD;
    const __half* Bg = g_Vh + (ll)b * TT * DD + h * DHD;
    const int tbase = tc * 512;

    float acc[4][8][4];
#pragma unroll
    for (int i = 0; i < 4; i++)
#pragma unroll
        for (int j = 0; j < 8; j++)
#pragma unroll
            for (int v = 0; v < 4; v++) acc[i][j][v] = 0.f;

    auto load_stage = [&](int s, int kc) {
        uint32_t st = sbase + s * KSTAGEB;
        const int t0 = tbase + kc * 64;
        const __half* gs[2] = { Ag, Bg };
#pragma unroll
        for (int sub = 0; sub < 2; sub++) {
            const __half* gg = gs[sub];
            uint32_t base = st + sub * KSUBT;
#pragma unroll
            for (int u = 0; u < 8; u++) {
                int idx = tid + u * 128;
                int r = idx >> 4, c = idx & 15;
                CP_ASYNC16(base + r * KPITCH + c * 16, gg + (ll)(t0 + r) * 1024 + c * 8);
            }
        }
        CP_COMMIT();
    };

    load_stage(0, 0);
    load_stage(1, 1);
    for (int kc = 0; kc < 8; kc++) {
        const int s = kc % NSTG;
        if (kc + 2 < 8) { load_stage((kc + 2) % NSTG, kc + 2); CP_WAIT(2); }
        else if (kc + 1 < 8) CP_WAIT(1);
        else                 CP_WAIT(0);
        __syncthreads();

        const uint32_t st = sbase + s * KSTAGEB;
        const uint32_t sA = st, sB = st + KSUBT;

#pragma unroll
        for (int ks = 0; ks < 4; ks++) {
            uint32_t a[4][4], bf[8][2];
#pragma unroll
            for (int mi = 0; mi < 4; mi++) {
                int i0 = wm * 64 + mi * 16;
                uint32_t off = (uint32_t)((ks * 16 + asrow) * KPITCH + (i0 + ascol) * 2);
                LDSM_X4_T(a[mi][0], a[mi][1], a[mi][2], a[mi][3], sA + off);
            }
#pragma unroll
            for (int np = 0; np < 4; np++) {
                int j0 = wn * 64 + np * 16;
                uint32_t off = (uint32_t)((ks * 16 + bsrow) * KPITCH + (j0 + bscol) * 2);
                LDSM_X4_T(bf[np*2][0], bf[np*2][1], bf[np*2+1][0], bf[np*2+1][1], sB + off);
            }
#pragma unroll
            for (int mi = 0; mi < 4; mi++)
#pragma unroll
                for (int nt = 0; nt < 8; nt++)
                    MMA_F16(acc[mi][nt], a[mi], bf[nt]);
        }
        __syncthreads();
    }

    float* Cp = g_Kvpart + ((ll)tc * 32 + z) * 16384;
#pragma unroll
    for (int mi = 0; mi < 4; mi++) {
        int row = wm * 64 + mi * 16 + g;
#pragma unroll
        for (int nt = 0; nt < 8; nt++) {
            int col = wn * 64 + nt * 8 + tig * 2;
            *(float2*)&Cp[row * 128 + col]       = make_float2(acc[mi][nt][0], acc[mi][nt][1]);
            *(float2*)&Cp[(row + 8) * 128 + col] = make_float2(acc[mi][nt][2], acc[mi][nt][3]);
        }
    }
}

// ---------------- Ksum partials from g_eK ----------------
__global__ __launch_bounds__(128) void ksum_kernel(void)
{
    const int z = blockIdx.x, ch = blockIdx.y;
    const int b = z >> 3, h = z & 7;
    const __half* p = g_eK + (ll)b * TT * DD + h * DHD + threadIdx.x;
    float s = 0.f;
    const int t0 = ch * 128;
    for (int t = 0; t < 128; t++)
        s += __half2float(p[(ll)(t0 + t) * 1024]);
    g_Ksumpart[((ll)ch * 32 + z) * 128 + threadIdx.x] = s;
}

// ---------------- reduce + normalize ----------------
__global__ __launch_bounds__(128) void kv_reduce_norm_kernel(void)
{
    const int j  = threadIdx.x;
    const int zi = blockIdx.x;
    const int z = zi >> 7, i = zi & 127;
    float kv = 0.f, s = 0.f;
#pragma unroll
    for (int tc = 0; tc < 8; tc++)
        kv += g_Kvpart[((ll)tc * 32 + z) * 16384 + i * 128 + j];
#pragma unroll
    for (int ch = 0; ch < 32; ch++)
        s += g_Ksumpart[((ll)ch * 32 + z) * 128 + i];
    g_Kvn[(ll)z * 16384 + i * 128 + j] = kv / s;
}

// ============================ converters ============================
__global__ __launch_bounds__(256) void convA2_h_kernel(const float* __restrict__ x0,
                                                       __half* __restrict__ y0,
                                                       const float* __restrict__ x1,
                                                       __half* __restrict__ y1, int n4)
{
    int i = blockIdx.x * 256 + threadIdx.x;
    const float* x = x0; __half* y = y0;
    if (i >= n4) { x = x1; y = y1; i -= n4; }
    if (i >= n4) return;
    float4 v = *(const float4*)&x[(ll)i * 4];
    *(__half2*)&y[(ll)i * 4]     = __floats2half2_rn(v.x, v.y);
    *(__half2*)&y[(ll)i * 4 + 2] = __floats2half2_rn(v.z, v.w);
}

__global__ __launch_bounds__(1024) void convWT_h_kernel(const float* __restrict__ W,
                                                        __half* __restrict__ y)
{
    __shared__ float ts[32][33];
    int tx = threadIdx.x & 31, ty = threadIdx.x >> 5;
    int k0 = blockIdx.y * 32, n0 = blockIdx.x * 32;
    ts[ty][tx] = W[(ll)(k0 + ty) * 1024 + n0 + tx];
    __syncthreads();
    y[(ll)(n0 + ty) * 1024 + k0 + tx] = __float2half_rn(ts[tx][ty]);
}

// ---------------- fp32 Z-GEMM with fused fp16-transposed epilogue ----------------
// Per z=b*8+h: C'[l][n] = sum_d Kvn[z][l][d] * wproj[h*128+d][n]   (M=128, N=1024, K=128)
// Output written TRANSPOSED as fp16 into ZT[b][n][h*128+l] (= Bw slot layout for the out GEMM).
#define BM 128
#define BN 128
#define BK 16
__global__ __launch_bounds__(256) void zgemm_kernel(const float* __restrict__ Kvn,
                                                    const float* __restrict__ Wp,
                                                    __half* __restrict__ ZT)
{
    const int z = blockIdx.z;
    const int b = z >> 3, h = z & 7;
    const float* A  = Kvn + (ll)z * 16384;               // [l][d], lda=128
    const float* Bm = Wp + (ll)h * 131072;               // [d][n], ldb=1024
    __half* Czt = ZT + (ll)b * 1048576 + h * 128;        // [n][h*128+l], pitch 1024

    __shared__ float As[BK][BM];
    __shared__ float Bs[BK][BN];
    const int tid = threadIdx.x;
    const int ty = tid >> 4, tx = tid & 15;
    const int n0 = blockIdx.x * BN;

    float acc[8][8];
#pragma unroll
    for (int i = 0; i < 8; i++)
#pragma unroll
        for (int j = 0; j < 8; j++) acc[i][j] = 0.f;

    for (int k0 = 0; k0 < 128; k0 += BK) {
#pragma unroll
        for (int u = 0; u < 2; u++) {
            int idx = tid + u * 256;
            int r = idx >> 2, c4 = (idx & 3) << 2;
            float4 v = *(const float4*)&A[(ll)r * 128 + k0 + c4];
            As[c4 + 0][r] = v.x; As[c4 + 1][r] = v.y;
            As[c4 + 2][r] = v.z; As[c4 + 3][r] = v.w;
        }
#pragma unroll
        for (int u = 0; u < 2; u++) {
            int idx = tid + u * 256;
            int r = idx >> 5, c4 = (idx & 31) << 2;
            *(float4*)&Bs[r][c4] = *(const float4*)&Bm[(ll)(k0 + r) * 1024 + n0 + c4];
        }
        __syncthreads();
#pragma unroll
        for (int k = 0; k < BK; k++) {
            float4 a0 = *(const float4*)&As[k][ty * 8];
            float4 a1 = *(const float4*)&As[k][ty * 8 + 4];
            float4 b0 = *(const float4*)&Bs[k][tx * 8];
            float4 b1 = *(const float4*)&Bs[k][tx * 8 + 4];
            float a[8] = {a0.x,a0.y,a0.z,a0.w,a1.x,a1.y,a1.z,a1.w};
            float bb[8] = {b0.x,b0.y,b0.z,b0.w,b1.x,b1.y,b1.z,b1.w};
#pragma unroll
            for (int i = 0; i < 8; i++)
#pragma unroll
                for (int j = 0; j < 8; j++) acc[i][j] += a[i] * bb[j];
        }
        __syncthreads();
    }
    // fused epilogue: ZT[n][l] = half(acc[l][n])
#pragma unroll
    for (int j = 0; j < 8; j++) {
        ll nrow = (ll)(n0 + tx * 8 + j) * 1024;
#pragma unroll
        for (int i = 0; i < 8; i++)
            Czt[nrow + ty * 8 + i] = __float2half_rn(acc[i][j]);
    }
}

// ---------------- launch ----------------
extern "C" void kernel_launch(void* const* d_in, const int* in_sizes, int n_in,
                              void* d_out, int out_size)
{
    const float* query = (const float*)d_in[0];
    const float* key   = (const float*)d_in[1];
    const float* wq    = (const float*)d_in[2];
    const float* wk    = (const float*)d_in[3];
    const float* wv    = (const float*)d_in[4];
    const float* wproj = (const float*)d_in[5];
    float* out = (float*)d_out;

    float *Kvn;
    __half *Aq, *Ak, *Qs, *Bw, *eK, *Vh;
    cudaGetSymbolAddress((void**)&Kvn, g_Kvn);
    cudaGetSymbolAddress((void**)&Aq,  g_Aq);
    cudaGetSymbolAddress((void**)&Ak,  g_Ak);
    cudaGetSymbolAddress((void**)&Qs,  g_Qs);
    cudaGetSymbolAddress((void**)&Bw,  g_Bw);
    cudaGetSymbolAddress((void**)&eK,  g_eK);
    cudaGetSymbolAddress((void**)&Vh,  g_Vh);

    cudaFuncSetAttribute(phmma_kernel, cudaFuncAttributeMaxDynamicSharedMemorySize, GEMM_SMEM);
    cudaFuncSetAttribute(kv16_kernel,  cudaFuncAttributeMaxDynamicSharedMemorySize, KV_SMEM);

    int nsm = 148;
    cudaDeviceGetAttribute(&nsm, cudaDevAttrMultiProcessorCount, 0);
    const int pgrid = nsm * 2;

    const int MBT = BATCH * TT;                 // 16384
    const int actN4 = MBT * DD / 4;
    dim3 gconvA2((2 * actN4 + 255) / 256), bconvA(256);
    dim3 gconvW1(32, 32, 1), bconvW(1024);

    // ---- converts: query+key fp16 (one launch), weights wq/wk/wv transposed fp16 ----
    convA2_h_kernel<<<gconvA2, bconvA>>>(query, Aq, key, Ak, actN4);
    convWT_h_kernel<<<gconvW1, bconvW>>>(wq, Bw);
    convWT_h_kernel<<<gconvW1, bconvW>>>(wk, Bw + 1ll * 1048576);
    convWT_h_kernel<<<gconvW1, bconvW>>>(wv, Bw + 2ll * 1048576);

    // ---- persistent QKV mega-GEMM: softmax(Q) fp16 | exp(K) fp16 | V fp16 ----
    GemmJobs jq;
    jq.A[0] = Aq;  jq.A[1] = Ak;  jq.A[2] = Ak;
    jq.B[0] = Bw;  jq.B[1] = Bw + 1048576; jq.B[2] = Bw + 2097152;
    jq.C[0] = Qs;  jq.C[1] = eK;  jq.C[2] = Vh;
    jq.epi[0] = 3; jq.epi[1] = 1; jq.epi[2] = 2;
    jq.total = 3072; jq.bShift = -1; jq.bStride = 0;
    phmma_kernel<<<pgrid, 128, GEMM_SMEM>>>(jq);

    // ---- kv aggregation (fp16 HMMA) + Ksum + reduce/normalize ----
    kv16_kernel<<<dim3(32, 8), 128, KV_SMEM>>>();
    ksum_kernel<<<dim3(32, 32), 128>>>();
    kv_reduce_norm_kernel<<<dim3(32 * 128), 128>>>();

    // ---- Z-GEMM with fused fp16-transpose epilogue: writes Bw directly ----
    dim3 gz(8, 1, 32);
    zgemm_kernel<<<gz, 256>>>(Kvn, wproj, Bw);

    // ---- persistent OUT GEMM: out[b] = Qs[b] @ Z[b] ----
    GemmJobs jo;
    jo.A[0] = Qs;  jo.A[1] = Qs;  jo.A[2] = Qs;
    jo.B[0] = Bw;  jo.B[1] = Bw;  jo.B[2] = Bw;
    jo.C[0] = out; jo.C[1] = out; jo.C[2] = out;
    jo.epi[0] = 0; jo.epi[1] = 0; jo.epi[2] = 0;
    jo.total = 1024; jo.bShift = 5; jo.bStride = 1048576;   // b = m_idx>>5
    phmma_kernel<<<pgrid, 128, GEMM_SMEM>>>(jo);
}

// round 14
// speedup vs baseline: 1.0406x; 1.0178x over previous
#include <cuda_runtime.h>
#include <cuda_fp16.h>
#include <math.h>
#include <stdint.h>

// Problem constants
#define BATCH 4
#define TT    4096
#define DD    1024
#define LATD  1024
#define NH    8
#define DHD   128

typedef long long ll;

// ---------------- scratch (device globals; no allocation allowed) ----------------
__device__ float g_Kvpart[(size_t)8 * 32 * 128 * 128];    // [tc][z][i][j]
__device__ float g_Ksumpart[(size_t)8 * 32 * 128];        // [tc][z][i]
// fp16 buffers
__device__ __half g_Aq[(size_t)BATCH * TT * DD];   // query fp16
__device__ __half g_Ak[(size_t)BATCH * TT * DD];   // key fp16
__device__ __half g_Qs[(size_t)BATCH * TT * DD];   // softmax(Q) fp16 (Q-GEMM epilogue)
__device__ __half g_Bw[(size_t)4 * DD * DD];       // weight^T fp16: wq,wk,wv | ZT(4 batches)
__device__ __half g_eK[(size_t)BATCH * TT * DD];   // exp(K) fp16 [b][t][1024]
__device__ __half g_Vh[(size_t)BATCH * TT * DD];   // V fp16 [b][t][1024]

// ============================ PTX helpers ============================
__device__ __forceinline__ uint32_t smem_u32(const void* p) {
    uint32_t a;
    asm("{ .reg .u64 t; cvta.to.shared.u64 t, %1; cvt.u32.u64 %0, t; }" : "=r"(a) : "l"(p));
    return a;
}
#define CP_ASYNC16(s, g) asm volatile("cp.async.cg.shared.global [%0], [%1], 16;" :: "r"(s), "l"(g))
#define CP_COMMIT() asm volatile("cp.async.commit_group;" ::: "memory")
#define CP_WAIT(n)  asm volatile("cp.async.wait_group %0;" :: "n"(n) : "memory")

#define LDSM_X4(r0, r1, r2, r3, a) \
    asm volatile("ldmatrix.sync.aligned.m8n8.x4.shared.b16 {%0,%1,%2,%3}, [%4];" \
                 : "=r"(r0), "=r"(r1), "=r"(r2), "=r"(r3) : "r"(a))

#define LDSM_X4_T(r0, r1, r2, r3, a) \
    asm volatile("ldmatrix.sync.aligned.m8n8.x4.trans.shared.b16 {%0,%1,%2,%3}, [%4];" \
                 : "=r"(r0), "=r"(r1), "=r"(r2), "=r"(r3) : "r"(a))

#define MMA_F16(c, a, b) \
    asm volatile("mma.sync.aligned.m16n8k16.row.col.f32.f16.f16.f32 " \
                 "{%0,%1,%2,%3}, {%4,%5,%6,%7}, {%8,%9}, {%0,%1,%2,%3};" \
                 : "+f"((c)[0]), "+f"((c)[1]), "+f"((c)[2]), "+f"((c)[3]) \
                 : "r"((a)[0]), "r"((a)[1]), "r"((a)[2]), "r"((a)[3]), \
                   "r"((b)[0]), "r"((b)[1]))

// ============================ persistent single-fp16 HMMA GEMM ============================
#define NKC 16
#define ROWB 144                 // 128B data + 16B pad
#define SUBT (128 * ROWB)        // 18432
#define STAGEB (2 * SUBT)        // A, B = 36864
#define NSTG 3
#define GEMM_SMEM (NSTG * STAGEB)   // 110592

struct GemmJobs {
    const __half* A[3];
    const __half* B[3];
    void*         C[3];
    int           epi[3];     // 0 fp32, 1 fp16 exp, 2 fp16, 3 fp16 softmax-over-cols
    int total;
    int bShift;
    ll  bStride;
};

__global__ __launch_bounds__(128, 2) void phmma_kernel(GemmJobs J)
{
    extern __shared__ char dsm[];
    const uint32_t sbase = smem_u32(dsm);
    const int tid = threadIdx.x;
    const int wid = tid >> 5, lane = tid & 31;
    const int wm = wid & 1, wn = wid >> 1;
    const int arow_l = lane & 15, aseg = lane >> 4;
    const int brow_l = (lane & 7) + ((lane >> 4) << 3), bseg = (lane >> 3) & 1;
    const int g = lane >> 2, tig = lane & 3;

    for (int t = blockIdx.x; t < J.total; t += gridDim.x) {
        const int job = t >> 10;
        const int rem = t & 1023;
        const int mI = rem >> 3, nI = rem & 7;

        const __half* Ap = J.A[job] + (ll)mI * 131072;
        const __half* Bp = J.B[job];
        if (J.bShift >= 0) Bp += (ll)(mI >> J.bShift) * J.bStride;
        Bp += (ll)nI * 131072;
        const ll cOff = (ll)mI * 131072 + nI * 128;

        float acc[4][8][4];
#pragma unroll
        for (int i = 0; i < 4; i++)
#pragma unroll
            for (int j = 0; j < 8; j++)
#pragma unroll
                for (int v = 0; v < 4; v++) acc[i][j][v] = 0.f;

        auto load_stage = [&](int s, int kc) {
            uint32_t st = sbase + s * STAGEB;
            const int k0 = kc * 64;
            const __half* gs[2] = { Ap + k0, Bp + k0 };
#pragma unroll
            for (int sub = 0; sub < 2; sub++) {
                const __half* gg = gs[sub];
                uint32_t base = st + sub * SUBT;
#pragma unroll
                for (int u = 0; u < 8; u++) {
                    int idx = tid + u * 128;
                    int r = idx >> 3, ch = idx & 7;
                    CP_ASYNC16(base + r * ROWB + ch * 16, gg + (ll)r * 1024 + ch * 8);
                }
            }
            CP_COMMIT();
        };

        load_stage(0, 0);
        load_stage(1, 1);
        for (int kc = 0; kc < NKC; kc++) {
            const int s = kc % NSTG;
            if (kc + 2 < NKC) { load_stage((kc + 2) % NSTG, kc + 2); CP_WAIT(2); }
            else if (kc + 1 < NKC) CP_WAIT(1);
            else                   CP_WAIT(0);
            __syncthreads();

            const uint32_t st = sbase + s * STAGEB;
            const uint32_t sA = st, sB = st + SUBT;

#pragma unroll
            for (int ks = 0; ks < 4; ks++) {
                uint32_t a[4][4], b[8][2];
#pragma unroll
                for (int mi = 0; mi < 4; mi++) {
                    uint32_t off = (uint32_t)((wm * 64 + mi * 16 + arow_l) * ROWB + ks * 32 + aseg * 16);
                    LDSM_X4(a[mi][0], a[mi][1], a[mi][2], a[mi][3], sA + off);
                }
#pragma unroll
                for (int np = 0; np < 4; np++) {
                    uint32_t off = (uint32_t)((wn * 64 + np * 16 + brow_l) * ROWB + ks * 32 + bseg * 16);
                    LDSM_X4(b[np*2][0], b[np*2][1], b[np*2+1][0], b[np*2+1][1], sB + off);
                }
#pragma unroll
                for (int mi = 0; mi < 4; mi++)
#pragma unroll
                    for (int nt = 0; nt < 8; nt++)
                        MMA_F16(acc[mi][nt], a[mi], b[nt]);
            }
            __syncthreads();
        }

        const int ep = J.epi[job];
        if (ep == 0) {
            float* Cf = (float*)J.C[job] + cOff;
#pragma unroll
            for (int mi = 0; mi < 4; mi++) {
                int row = wm * 64 + mi * 16 + g;
#pragma unroll
                for (int nt = 0; nt < 8; nt++) {
                    int col = wn * 64 + nt * 8 + tig * 2;
                    *(float2*)&Cf[(ll)row * 1024 + col]       = make_float2(acc[mi][nt][0], acc[mi][nt][1]);
                    *(float2*)&Cf[(ll)(row + 8) * 1024 + col] = make_float2(acc[mi][nt][2], acc[mi][nt][3]);
                }
            }
        } else if (ep == 1 || ep == 2) {
            __half* Ch = (__half*)J.C[job] + cOff;
#pragma unroll
            for (int mi = 0; mi < 4; mi++) {
                int row = wm * 64 + mi * 16 + g;
#pragma unroll
                for (int nt = 0; nt < 8; nt++) {
                    int col = wn * 64 + nt * 8 + tig * 2;
                    float a0 = acc[mi][nt][0], a1 = acc[mi][nt][1];
                    float a2 = acc[mi][nt][2], a3 = acc[mi][nt][3];
                    if (ep == 1) { a0 = expf(a0); a1 = expf(a1); a2 = expf(a2); a3 = expf(a3); }
                    *(__half2*)&Ch[(ll)row * 1024 + col]       = __floats2half2_rn(a0, a1);
                    *(__half2*)&Ch[(ll)(row + 8) * 1024 + col] = __floats2half2_rn(a2, a3);
                }
            }
        } else {
            // ep == 3: fused softmax over tile's 128 columns (one head slice)
            float* smax = (float*)dsm;
            float* ssum = smax + 256;
#pragma unroll
            for (int mi = 0; mi < 4; mi++) {
                float m0 = acc[mi][0][0], m1 = acc[mi][0][2];
#pragma unroll
                for (int nt = 0; nt < 8; nt++) {
                    m0 = fmaxf(m0, fmaxf(acc[mi][nt][0], acc[mi][nt][1]));
                    m1 = fmaxf(m1, fmaxf(acc[mi][nt][2], acc[mi][nt][3]));
                }
                m0 = fmaxf(m0, __shfl_xor_sync(0xffffffffu, m0, 1));
                m0 = fmaxf(m0, __shfl_xor_sync(0xffffffffu, m0, 2));
                m1 = fmaxf(m1, __shfl_xor_sync(0xffffffffu, m1, 1));
                m1 = fmaxf(m1, __shfl_xor_sync(0xffffffffu, m1, 2));
                if (tig == 0) {
                    int lr = wm * 64 + mi * 16 + g;
                    smax[wn * 128 + lr]     = m0;
                    smax[wn * 128 + lr + 8] = m1;
                }
            }
            __syncthreads();
#pragma unroll
            for (int mi = 0; mi < 4; mi++) {
                int lr = wm * 64 + mi * 16 + g;
                float M0 = fmaxf(smax[lr],     smax[128 + lr]);
                float M1 = fmaxf(smax[lr + 8], smax[128 + lr + 8]);
                float s0 = 0.f, s1 = 0.f;
#pragma unroll
                for (int nt = 0; nt < 8; nt++) {
                    acc[mi][nt][0] = expf(acc[mi][nt][0] - M0);
                    acc[mi][nt][1] = expf(acc[mi][nt][1] - M0);
                    acc[mi][nt][2] = expf(acc[mi][nt][2] - M1);
                    acc[mi][nt][3] = expf(acc[mi][nt][3] - M1);
                    s0 += acc[mi][nt][0] + acc[mi][nt][1];
                    s1 += acc[mi][nt][2] + acc[mi][nt][3];
                }
                s0 += __shfl_xor_sync(0xffffffffu, s0, 1);
                s0 += __shfl_xor_sync(0xffffffffu, s0, 2);
                s1 += __shfl_xor_sync(0xffffffffu, s1, 1);
                s1 += __shfl_xor_sync(0xffffffffu, s1, 2);
                if (tig == 0) {
                    ssum[wn * 128 + lr]     = s0;
                    ssum[wn * 128 + lr + 8] = s1;
                }
            }
            __syncthreads();
            __half* Ch = (__half*)J.C[job] + cOff;
#pragma unroll
            for (int mi = 0; mi < 4; mi++) {
                int lr = wm * 64 + mi * 16 + g;
                float i0 = 1.f / (ssum[lr]     + ssum[128 + lr]);
                float i1 = 1.f / (ssum[lr + 8] + ssum[128 + lr + 8]);
#pragma unroll
                for (int nt = 0; nt < 8; nt++) {
                    int col = wn * 64 + nt * 8 + tig * 2;
                    *(__half2*)&Ch[(ll)lr * 1024 + col] =
                        __floats2half2_rn(acc[mi][nt][0] * i0, acc[mi][nt][1] * i0);
                    *(__half2*)&Ch[(ll)(lr + 8) * 1024 + col] =
                        __floats2half2_rn(acc[mi][nt][2] * i1, acc[mi][nt][3] * i1);
                }
            }
            __syncthreads();
        }
    }
}

// ============================ kv fp16 HMMA + fused Ksum ============================
// Kvpart[tc][z] = expK^T x V over 512 t; Ksumpart[tc][z][i] = sum_t expK (from smem).
#define KPITCH 272
#define KSUBT (64 * KPITCH)
#define KSTAGEB (2 * KSUBT)
#define KV_SMEM (NSTG * KSTAGEB)

__global__ __launch_bounds__(128, 2) void kv16_kernel(void)
{
    extern __shared__ char dsm[];
    const uint32_t sbase = smem_u32(dsm);
    const int tid = threadIdx.x;
    const int wid = tid >> 5, lane = tid & 31;
    const int wm = wid & 1, wn = wid >> 1;
    const int z = blockIdx.x, tc = blockIdx.y;
    const int b = z >> 3, h = z & 7;

    const int asrow = (lane & 7) + ((lane >> 4) << 3);
    const int ascol = ((lane >> 3) & 1) * 8;
    const int bsrow = (lane & 7) + (((lane >> 3) & 1) << 3);
    const int bscol = (lane >> 4) * 8;
    const int g = lane >> 2, tig = lane & 3;

    const __half* Ag = g_eK + (ll)b * TT * DD + h * DHD;
    const __half* Bg = g_Vh + (ll)b * TT * DD + h * DHD;
    const int tbase = tc * 512;

    float acc[4][8][4];
#pragma unroll
    for (int i = 0; i < 4; i++)
#pragma unroll
        for (int j = 0; j < 8; j++)
#pragma unroll
            for (int v = 0; v < 4; v++) acc[i][j][v] = 0.f;
    float ksum = 0.f;   // column tid of eK, summed over all 512 t

    auto load_stage = [&](int s, int kc) {
        uint32_t st = sbase + s * KSTAGEB;
        const int t0 = tbase + kc * 64;
        const __half* gs[2] = { Ag, Bg };
#pragma unroll
        for (int sub = 0; sub < 2; sub++) {
            const __half* gg = gs[sub];
            uint32_t base = st + sub * KSUBT;
#pragma unroll
            for (int u = 0; u < 8; u++) {
                int idx = tid + u * 128;
                int r = idx >> 4, c = idx & 15;
                CP_ASYNC16(base + r * KPITCH + c * 16, gg + (ll)(t0 + r) * 1024 + c * 8);
            }
        }
        CP_COMMIT();
    };

    load_stage(0, 0);
    load_stage(1, 1);
    for (int kc = 0; kc < 8; kc++) {
        const int s = kc % NSTG;
        if (kc + 2 < 8) { load_stage((kc + 2) % NSTG, kc + 2); CP_WAIT(2); }
        else if (kc + 1 < 8) CP_WAIT(1);
        else                 CP_WAIT(0);
        __syncthreads();

        const uint32_t st = sbase + s * KSTAGEB;
        const uint32_t sA = st, sB = st + KSUBT;

        // fused Ksum: sum eK column tid over this stage's 64 t-rows (smem-resident)
        {
            const char* sAp = dsm + (size_t)s * KSTAGEB + (size_t)tid * 2;
#pragma unroll 4
            for (int r = 0; r < 64; r++)
                ksum += __half2float(*(const __half*)(sAp + r * KPITCH));
        }

#pragma unroll
        for (int ks = 0; ks < 4; ks++) {
            uint32_t a[4][4], bf[8][2];
#pragma unroll
            for (int mi = 0; mi < 4; mi++) {
                int i0 = wm * 64 + mi * 16;
                uint32_t off = (uint32_t)((ks * 16 + asrow) * KPITCH + (i0 + ascol) * 2);
                LDSM_X4_T(a[mi][0], a[mi][1], a[mi][2], a[mi][3], sA + off);
            }
#pragma unroll
            for (int np = 0; np < 4; np++) {
                int j0 = wn * 64 + np * 16;
                uint32_t off = (uint32_t)((ks * 16 + bsrow) * KPITCH + (j0 + bscol) * 2);
                LDSM_X4_T(bf[np*2][0], bf[np*2][1], bf[np*2+1][0], bf[np*2+1][1], sB + off);
            }
#pragma unroll
            for (int mi = 0; mi < 4; mi++)
#pragma unroll
                for (int nt = 0; nt < 8; nt++)
                    MMA_F16(acc[mi][nt], a[mi], bf[nt]);
        }
        __syncthreads();
    }

    float* Cp = g_Kvpart + ((ll)tc * 32 + z) * 16384;
#pragma unroll
    for (int mi = 0; mi < 4; mi++) {
        int row = wm * 64 + mi * 16 + g;
#pragma unroll
        for (int nt = 0; nt < 8; nt++) {
            int col = wn * 64 + nt * 8 + tig * 2;
            *(float2*)&Cp[row * 128 + col]       = make_float2(acc[mi][nt][0], acc[mi][nt][1]);
            *(float2*)&Cp[(row + 8) * 128 + col] = make_float2(acc[mi][nt][2], acc[mi][nt][3]);
        }
    }
    g_Ksumpart[((ll)tc * 32 + z) * 128 + tid] = ksum;
}

// ============================ converters ============================
// two fp32->fp16 conversions in one launch, 8 floats/thread
__global__ __launch_bounds__(256) void convA2_h_kernel(const float* __restrict__ x0,
                                                       __half* __restrict__ y0,
                                                       const float* __restrict__ x1,
                                                       __half* __restrict__ y1, int n8)
{
    int i = blockIdx.x * 256 + threadIdx.x;
    const float* x = x0; __half* y = y0;
    if (i >= n8) { x = x1; y = y1; i -= n8; }
    if (i >= n8) return;
    float4 v0 = *(const float4*)&x[(ll)i * 8];
    float4 v1 = *(const float4*)&x[(ll)i * 8 + 4];
    *(__half2*)&y[(ll)i * 8]     = __floats2half2_rn(v0.x, v0.y);
    *(__half2*)&y[(ll)i * 8 + 2] = __floats2half2_rn(v0.z, v0.w);
    *(__half2*)&y[(ll)i * 8 + 4] = __floats2half2_rn(v1.x, v1.y);
    *(__half2*)&y[(ll)i * 8 + 6] = __floats2half2_rn(v1.z, v1.w);
}

// three weight transposes in one launch (per-z pointer select; no OOB)
__global__ __launch_bounds__(1024) void convWT3_h_kernel(const float* __restrict__ w0,
                                                         const float* __restrict__ w1,
                                                         const float* __restrict__ w2,
                                                         __half* __restrict__ y)
{
    __shared__ float ts[32][33];
    const float* W = (blockIdx.z == 0) ? w0 : (blockIdx.z == 1) ? w1 : w2;
    __half* yz = y + (ll)blockIdx.z * 1048576;
    int tx = threadIdx.x & 31, ty = threadIdx.x >> 5;
    int k0 = blockIdx.y * 32, n0 = blockIdx.x * 32;
    ts[ty][tx] = W[(ll)(k0 + ty) * 1024 + n0 + tx];
    __syncthreads();
    yz[(ll)(n0 + ty) * 1024 + k0 + tx] = __float2half_rn(ts[tx][ty]);
}

// ---------------- Z-GEMM: fused partial-reduce + normalize + fp16-transposed epilogue ----------------
// Per z=b*8+h: A[l][d] = (sum_tc Kvpart[tc][z][l][d]) / (sum_tc Ksumpart[tc][z][l])
// C'[l][n] = A @ wproj[h*128:, :];  written transposed fp16 into ZT[b][n][h*128+l].
#define BM 128
#define BN 128
#define BK 16
__global__ __launch_bounds__(256) void zgemm_kernel(const float* __restrict__ Wp,
                                                    __half* __restrict__ ZT)
{
    const int z = blockIdx.z;
    const int b = z >> 3, h = z & 7;
    const float* Bm = Wp + (ll)h * 131072;               // [d][n], ldb=1024
    __half* Czt = ZT + (ll)b * 1048576 + h * 128;        // [n][h*128+l], pitch 1024

    __shared__ float As[BK][BM];
    __shared__ float Bs[BK][BN];
    __shared__ float sdiv[128];
    const int tid = threadIdx.x;
    const int ty = tid >> 4, tx = tid & 15;
    const int n0 = blockIdx.x * BN;

    if (tid < 128) {
        float s = 0.f;
#pragma unroll
        for (int tc = 0; tc < 8; tc++)
            s += g_Ksumpart[((ll)tc * 32 + z) * 128 + tid];
        sdiv[tid] = s;
    }
    __syncthreads();

    float acc[8][8];
#pragma unroll
    for (int i = 0; i < 8; i++)
#pragma unroll
        for (int j = 0; j < 8; j++) acc[i][j] = 0.f;

    for (int k0 = 0; k0 < 128; k0 += BK) {
#pragma unroll
        for (int u = 0; u < 2; u++) {
            int idx = tid + u * 256;
            int r = idx >> 2, c4 = (idx & 3) << 2;
            float4 v = make_float4(0.f, 0.f, 0.f, 0.f);
#pragma unroll
            for (int tc = 0; tc < 8; tc++) {
                const float4 p = *(const float4*)&g_Kvpart[(((ll)tc * 32 + z) << 14) + r * 128 + k0 + c4];
                v.x += p.x; v.y += p.y; v.z += p.z; v.w += p.w;
            }
            float s = sdiv[r];
            As[c4 + 0][r] = v.x / s; As[c4 + 1][r] = v.y / s;
            As[c4 + 2][r] = v.z / s; As[c4 + 3][r] = v.w / s;
        }
#pragma unroll
        for (int u = 0; u < 2; u++) {
            int idx = tid + u * 256;
            int r = idx >> 5, c4 = (idx & 31) << 2;
            *(float4*)&Bs[r][c4] = *(const float4*)&Bm[(ll)(k0 + r) * 1024 + n0 + c4];
        }
        __syncthreads();
#pragma unroll
        for (int k = 0; k < BK; k++) {
            float4 a0 = *(const float4*)&As[k][ty * 8];
            float4 a1 = *(const float4*)&As[k][ty * 8 + 4];
            float4 b0 = *(const float4*)&Bs[k][tx * 8];
            float4 b1 = *(const float4*)&Bs[k][tx * 8 + 4];
            float a[8] = {a0.x,a0.y,a0.z,a0.w,a1.x,a1.y,a1.z,a1.w};
            float bb[8] = {b0.x,b0.y,b0.z,b0.w,b1.x,b1.y,b1.z,b1.w};
#pragma unroll
            for (int i = 0; i < 8; i++)
#pragma unroll
                for (int j = 0; j < 8; j++) acc[i][j] += a[i] * bb[j];
        }
        __syncthreads();
    }
#pragma unroll
    for (int j = 0; j < 8; j++) {
        ll nrow = (ll)(n0 + tx * 8 + j) * 1024;
#pragma unroll
        for (int i = 0; i < 8; i++)
            Czt[nrow + ty * 8 + i] = __float2half_rn(acc[i][j]);
    }
}

// ---------------- launch ----------------
extern "C" void kernel_launch(void* const* d_in, const int* in_sizes, int n_in,
                              void* d_out, int out_size)
{
    const float* query = (const float*)d_in[0];
    const float* key   = (const float*)d_in[1];
    const float* wq    = (const float*)d_in[2];
    const float* wk    = (const float*)d_in[3];
    const float* wv    = (const float*)d_in[4];
    const float* wproj = (const float*)d_in[5];
    float* out = (float*)d_out;

    __half *Aq, *Ak, *Qs, *Bw;
    cudaGetSymbolAddress((void**)&Aq,  g_Aq);
    cudaGetSymbolAddress((void**)&Ak,  g_Ak);
    cudaGetSymbolAddress((void**)&Qs,  g_Qs);
    cudaGetSymbolAddress((void**)&Bw,  g_Bw);

    cudaFuncSetAttribute(phmma_kernel, cudaFuncAttributeMaxDynamicSharedMemorySize, GEMM_SMEM);
    cudaFuncSetAttribute(kv16_kernel,  cudaFuncAttributeMaxDynamicSharedMemorySize, KV_SMEM);

    int nsm = 148;
    cudaDeviceGetAttribute(&nsm, cudaDevAttrMultiProcessorCount, 0);
    const int pgrid = nsm * 2;

    const int MBT = BATCH * TT;                 // 16384
    const int actN8 = MBT * DD / 8;
    dim3 gconvA2((2 * actN8 + 255) / 256), bconvA(256);
    dim3 gconvW3(32, 32, 3), bconvW(1024);

    // ---- converts: query+key fp16 (one launch), wq/wk/wv transposed fp16 (one launch) ----
    convA2_h_kernel<<<gconvA2, bconvA>>>(query, Aq, key, Ak, actN8);
    convWT3_h_kernel<<<gconvW3, bconvW>>>(wq, wk, wv, Bw);

    // ---- persistent QKV mega-GEMM: softmax(Q) fp16 | exp(K) fp16 | V fp16 ----
    GemmJobs jq;
    jq.A[0] = Aq;  jq.A[1] = Ak;  jq.A[2] = Ak;
    jq.B[0] = Bw;  jq.B[1] = Bw + 1048576; jq.B[2] = Bw + 2097152;
    jq.C[0] = Qs;  jq.C[1] = (void*)0; jq.C[2] = (void*)0;
    {   // eK / Vh addresses
        __half *eK, *Vh;
        cudaGetSymbolAddress((void**)&eK, g_eK);
        cudaGetSymbolAddress((void**)&Vh, g_Vh);
        jq.C[1] = eK; jq.C[2] = Vh;
    }
    jq.epi[0] = 3; jq.epi[1] = 1; jq.epi[2] = 2;
    jq.total = 3072; jq.bShift = -1; jq.bStride = 0;
    phmma_kernel<<<pgrid, 128, GEMM_SMEM>>>(jq);

    // ---- kv aggregation + fused Ksum ----
    kv16_kernel<<<dim3(32, 8), 128, KV_SMEM>>>();

    // ---- Z-GEMM (fused reduce + normalize + fp16-transpose into Bw) ----
    dim3 gz(8, 1, 32);
    zgemm_kernel<<<gz, 256>>>(wproj, Bw);

    // ---- persistent OUT GEMM: out[b] = Qs[b] @ Z[b] ----
    GemmJobs jo;
    jo.A[0] = Qs;  jo.A[1] = Qs;  jo.A[2] = Qs;
    jo.B[0] = Bw;  jo.B[1] = Bw;  jo.B[2] = Bw;
    jo.C[0] = out; jo.C[1] = out; jo.C[2] = out;
    jo.epi[0] = 0; jo.epi[1] = 0; jo.epi[2] = 0;
    jo.total = 1024; jo.bShift = 5; jo.bStride = 1048576;
    phmma_kernel<<<pgrid, 128, GEMM_SMEM>>>(jo);
}